// round 2
// baseline (speedup 1.0000x reference)
#include <cuda_runtime.h>
#include <cuda_bf16.h>
#include <cstdint>

#define Nn 50000
#define Ee 800000
#define Dd 64
#define Ll 3
#define Gg 512
#define Ss 32
#define POOLW (2*Dd*Ll)   // 384

// Scratch (no allocations allowed): h ping buffer, aggregation buffer, pooled features
__device__ float g_h[Nn * Dd];
__device__ float g_agg[Nn * Dd];
__device__ float g_pool[Gg * POOLW];

// ---------------------------------------------------------------------------
// Edge scatter: agg[dst] += edge_weight * h[src]   (vector red.global.add.v4)
// 16 threads per edge, one float4 each.
// ---------------------------------------------------------------------------
__global__ __launch_bounds__(256) void scatter_kernel(
    const float4* __restrict__ h4, const float* __restrict__ ew,
    const int* __restrict__ src, const int* __restrict__ dst,
    float* __restrict__ agg)
{
    unsigned tid = blockIdx.x * 256u + threadIdx.x;
    unsigned e = tid >> 4;
    if (e >= Ee) return;
    int c = tid & 15;
    int s = __ldg(src + e);
    int d = __ldg(dst + e);
    float w = __ldg(ew + e);
    float4 v = h4[(size_t)s * 16 + c];
    v.x *= w; v.y *= w; v.z *= w; v.w *= w;
    float* addr = agg + (size_t)d * 64 + c * 4;
    asm volatile("red.global.add.v4.f32 [%0], {%1, %2, %3, %4};"
                 :: "l"(addr), "f"(v.x), "f"(v.y), "f"(v.z), "f"(v.w)
                 : "memory");
}

// ---------------------------------------------------------------------------
// Fused per-layer MLP:
//   z = (1+eps)*h + agg ; t = relu(BN(z@W1 + b1)) ; h' = relu(t@W2 + b2)
//   h_out <- h' ; pool[batch[r], layer*128 + c] += h' * mask[r]
// Block = 64 rows. 256 threads as 16x16 grid of 4x4 register tiles.
// ---------------------------------------------------------------------------
__global__ __launch_bounds__(256) void fused_mlp(
    const float* __restrict__ h_in, const float* __restrict__ agg,
    const float* __restrict__ W1, const float* __restrict__ b1,
    const float* __restrict__ gamma, const float* __restrict__ beta,
    const float* __restrict__ bn_mean, const float* __restrict__ bn_var,
    const float* __restrict__ W2, const float* __restrict__ b2,
    const float* __restrict__ eps_p,
    float* __restrict__ h_out, const float* __restrict__ mask,
    const int* __restrict__ batch, float* __restrict__ pool, int layer)
{
    extern __shared__ float sm[];
    float* sW1 = sm;                 // 4096 floats (64x64)
    float* sW2 = sm + 4096;          // 4096
    float* sZ  = sm + 8192;          // 64 x 65 padded = 4160
    float* sT  = sm + 8192 + 4160;   // 64 x 65 padded = 4160
    __shared__ float sScale[64], sShift[64], sB1[64], sB2[64];

    const int tid = threadIdx.x;
    const int rowBase = blockIdx.x * 64;
    const float epsv = 1.0f + __ldg(eps_p);

    // Load weights (float4, coalesced)
    float4* sW1v = (float4*)sW1;
    float4* sW2v = (float4*)sW2;
    const float4* W1v = (const float4*)W1;
    const float4* W2v = (const float4*)W2;
#pragma unroll
    for (int i = 0; i < 4; i++) {
        sW1v[tid + i * 256] = W1v[tid + i * 256];
        sW2v[tid + i * 256] = W2v[tid + i * 256];
    }
    if (tid < 64) {
        float sc = __ldg(gamma + tid) * rsqrtf(__ldg(bn_var + tid) + 1e-5f);
        sScale[tid] = sc;
        sShift[tid] = __ldg(beta + tid) - __ldg(bn_mean + tid) * sc;
        sB1[tid] = __ldg(b1 + tid);
        sB2[tid] = __ldg(b2 + tid);
    }

    // Load z tile = (1+eps)*h + agg
    const float4* h4 = (const float4*)h_in;
    const float4* a4 = (const float4*)agg;
#pragma unroll
    for (int i = 0; i < 4; i++) {
        int t = tid + i * 256;
        int r = t >> 4, c4 = t & 15;
        int gr = rowBase + r;
        float4 z = make_float4(0.f, 0.f, 0.f, 0.f);
        if (gr < Nn) {
            float4 hv = h4[(size_t)gr * 16 + c4];
            float4 av = a4[(size_t)gr * 16 + c4];
            z.x = fmaf(epsv, hv.x, av.x);
            z.y = fmaf(epsv, hv.y, av.y);
            z.z = fmaf(epsv, hv.z, av.z);
            z.w = fmaf(epsv, hv.w, av.w);
        }
        float* dstp = sZ + r * 65 + c4 * 4;
        dstp[0] = z.x; dstp[1] = z.y; dstp[2] = z.z; dstp[3] = z.w;
    }
    __syncthreads();

    const int tx = tid & 15, ty = tid >> 4;
    const int c0 = tx * 4, r0 = ty * 4;

    // GEMM1: acc = z @ W1
    float acc[4][4] = {};
#pragma unroll 8
    for (int k = 0; k < 64; k++) {
        float4 bv = sW1v[k * 16 + tx];
        float bb[4] = {bv.x, bv.y, bv.z, bv.w};
#pragma unroll
        for (int i = 0; i < 4; i++) {
            float a = sZ[(r0 + i) * 65 + k];
#pragma unroll
            for (int j = 0; j < 4; j++) acc[i][j] = fmaf(a, bb[j], acc[i][j]);
        }
    }

    // +b1, BN(eval), ReLU -> sT
#pragma unroll
    for (int i = 0; i < 4; i++) {
#pragma unroll
        for (int j = 0; j < 4; j++) {
            int c = c0 + j;
            float v = acc[i][j] + sB1[c];
            v = fmaf(v, sScale[c], sShift[c]);
            sT[(r0 + i) * 65 + c] = fmaxf(v, 0.f);
        }
    }
    __syncthreads();

    // GEMM2: acc2 = t @ W2
    float acc2[4][4] = {};
#pragma unroll 8
    for (int k = 0; k < 64; k++) {
        float4 bv = sW2v[k * 16 + tx];
        float bb[4] = {bv.x, bv.y, bv.z, bv.w};
#pragma unroll
        for (int i = 0; i < 4; i++) {
            float a = sT[(r0 + i) * 65 + k];
#pragma unroll
            for (int j = 0; j < 4; j++) acc2[i][j] = fmaf(a, bb[j], acc2[i][j]);
        }
    }

    // +b2, ReLU -> stage into sOut (reuse sZ region, contiguous stride 64).
    // Safe: all sZ reads completed before the previous __syncthreads.
    float* sOut = sZ;
#pragma unroll
    for (int i = 0; i < 4; i++)
#pragma unroll
        for (int j = 0; j < 4; j++)
            sOut[(r0 + i) * 64 + c0 + j] = fmaxf(acc2[i][j] + sB2[c0 + j], 0.f);
    __syncthreads();

    // Global write (coalesced float4) + pooled add via atomics
    float4* sOut4 = (float4*)sOut;
    float4* ho4 = (float4*)h_out;
#pragma unroll
    for (int i = 0; i < 4; i++) {
        int t = tid + i * 256;
        int r = t >> 4, c4 = t & 15;
        int gr = rowBase + r;
        if (gr < Nn) {
            float4 v = sOut4[r * 16 + c4];
            ho4[(size_t)gr * 16 + c4] = v;
            float w = __ldg(mask + gr);
            if (w != 0.f) {
                float* addr = pool + (size_t)__ldg(batch + gr) * POOLW + layer * 128 + c4 * 4;
                atomicAdd(addr + 0, v.x * w);
                atomicAdd(addr + 1, v.y * w);
                atomicAdd(addr + 2, v.z * w);
                atomicAdd(addr + 3, v.w * w);
            }
        }
    }
}

// ---------------------------------------------------------------------------
// Center-node gather: pool[g, layer*128 + 64 + c] = h[mapping[g], c]
// ---------------------------------------------------------------------------
__global__ __launch_bounds__(256) void center_kernel(
    const float4* __restrict__ h4, const int* __restrict__ mapping,
    float4* __restrict__ pool4, int layer)
{
    int t = blockIdx.x * 256 + threadIdx.x;
    if (t >= Gg * 16) return;
    int g = t >> 4, c = t & 15;
    int m = __ldg(mapping + g);
    pool4[g * (POOLW / 4) + layer * 32 + 16 + c] = h4[(size_t)m * 16 + c];
}

// ---------------------------------------------------------------------------
// Final projection: out[g, s] = pool[g, :] @ lin_w[:, s] + lin_b[s]
// 4 graphs per 128-thread block, 1 lane per output column.
// ---------------------------------------------------------------------------
__global__ __launch_bounds__(128) void final_kernel(
    const float* __restrict__ pool, const float* __restrict__ lw,
    const float* __restrict__ lb, float* __restrict__ out)
{
    int g = blockIdx.x * 4 + (threadIdx.x >> 5);
    int s = threadIdx.x & 31;
    const float* pr = pool + (size_t)g * POOLW;
    float acc = __ldg(lb + s);
#pragma unroll 4
    for (int k = 0; k < POOLW; k++)
        acc = fmaf(__ldg(pr + k), __ldg(lw + k * Ss + s), acc);
    out[g * Ss + s] = acc;
}

extern "C" void kernel_launch(void* const* d_in, const int* in_sizes, int n_in,
                              void* d_out, int out_size)
{
    const float* x       = (const float*)d_in[0];
    const float* ew      = (const float*)d_in[1];
    const float* mask    = (const float*)d_in[2];
    const float* W1      = (const float*)d_in[3];
    const float* b1      = (const float*)d_in[4];
    const float* gamma   = (const float*)d_in[5];
    const float* beta    = (const float*)d_in[6];
    const float* bn_mean = (const float*)d_in[7];
    const float* bn_var  = (const float*)d_in[8];
    const float* W2      = (const float*)d_in[9];
    const float* b2      = (const float*)d_in[10];
    const float* eps     = (const float*)d_in[11];
    const float* lin_w   = (const float*)d_in[12];
    const float* lin_b   = (const float*)d_in[13];
    const int* edge_index = (const int*)d_in[14];
    const int* batch      = (const int*)d_in[15];
    const int* mapping    = (const int*)d_in[16];
    float* out = (float*)d_out;

    float *hbuf = nullptr, *aggbuf = nullptr, *poolbuf = nullptr;
    (void)cudaGetSymbolAddress((void**)&hbuf, g_h);
    (void)cudaGetSymbolAddress((void**)&aggbuf, g_agg);
    (void)cudaGetSymbolAddress((void**)&poolbuf, g_pool);

    const int SMEM_BYTES = (4096 + 4096 + 4160 + 4160) * (int)sizeof(float); // 66048
    (void)cudaFuncSetAttribute(fused_mlp, cudaFuncAttributeMaxDynamicSharedMemorySize, SMEM_BYTES);

    cudaMemsetAsync(poolbuf, 0, (size_t)Gg * POOLW * sizeof(float));

    const float* h = x;
    for (int l = 0; l < Ll; l++) {
        cudaMemsetAsync(aggbuf, 0, (size_t)Nn * Dd * sizeof(float));
        scatter_kernel<<<(Ee * 16 + 255) / 256, 256>>>(
            (const float4*)h, ew, edge_index, edge_index + Ee, aggbuf);
        fused_mlp<<<(Nn + 63) / 64, 256, SMEM_BYTES>>>(
            h, aggbuf,
            W1 + l * Dd * Dd, b1 + l * Dd,
            gamma + l * Dd, beta + l * Dd, bn_mean + l * Dd, bn_var + l * Dd,
            W2 + l * Dd * Dd, b2 + l * Dd,
            eps + l,
            hbuf, mask, batch, poolbuf, l);
        center_kernel<<<(Gg * 16 + 255) / 256, 256>>>(
            (const float4*)hbuf, mapping, (float4*)poolbuf, l);
        h = hbuf;
    }
    final_kernel<<<Gg / 4, 128>>>(poolbuf, lin_w, lin_b, out);
}

// round 4
// speedup vs baseline: 1.0894x; 1.0894x over previous
#include <cuda_runtime.h>
#include <cuda_bf16.h>
#include <cstdint>

#define Nn 50000
#define Ee 800000
#define Dd 64
#define Ll 3
#define Gg 512
#define Ss 32
#define POOLW (2*Dd*Ll)   // 384
#define EQ (Ee/4)         // 200000 edges per quarter

// Scratch (no allocations allowed)
__device__ float g_h[Nn * Dd];
__device__ float g_agg[Nn * Dd];
__device__ float g_pool[Gg * POOLW];

// ---------------------------------------------------------------------------
// Edge scatter: agg[dst] += edge_weight * h[src]
// 16 threads per edge-slot; each thread processes 4 edges (front-batched
// loads -> MLP=4 to hide L2 latency). Vector red.global.add.v4.f32.
// ---------------------------------------------------------------------------
__global__ __launch_bounds__(256) void scatter_kernel(
    const float4* __restrict__ h4, const float* __restrict__ ew,
    const int* __restrict__ src, const int* __restrict__ dst,
    float* __restrict__ agg)
{
    unsigned tid = blockIdx.x * 256u + threadIdx.x;
    unsigned e0 = tid >> 4;
    if (e0 >= EQ) return;
    const int c = tid & 15;

    int s[4], d[4]; float w[4];
#pragma unroll
    for (int q = 0; q < 4; q++) {
        unsigned e = e0 + q * (unsigned)EQ;
        s[q] = __ldg(src + e);
        d[q] = __ldg(dst + e);
        w[q] = __ldg(ew + e);
    }
    float4 v[4];
#pragma unroll
    for (int q = 0; q < 4; q++)
        v[q] = h4[(size_t)s[q] * 16 + c];
#pragma unroll
    for (int q = 0; q < 4; q++) {
        float4 t = v[q];
        t.x *= w[q]; t.y *= w[q]; t.z *= w[q]; t.w *= w[q];
        float* addr = agg + (size_t)d[q] * 64 + c * 4;
        asm volatile("red.global.add.v4.f32 [%0], {%1, %2, %3, %4};"
                     :: "l"(addr), "f"(t.x), "f"(t.y), "f"(t.z), "f"(t.w)
                     : "memory");
    }
}

// ---------------------------------------------------------------------------
// Fused per-layer MLP with packed fp32x2 FMA (FFMA2):
//   z = (1+eps)*h + agg ; t = relu(BN(z@W1 + b1)) ; h' = relu(t@W2 + b2)
//   h_out <- h' ; pool[batch[r], layer*128 + c] += h' * mask[r]
// Block = 64 rows. 256 threads as 16x16 grid of 4x4 register tiles.
// Accumulators live as f32x2 pairs (two output columns per 64-bit reg).
// ---------------------------------------------------------------------------
__global__ __launch_bounds__(256) void fused_mlp(
    const float* __restrict__ h_in, const float* __restrict__ agg,
    const float* __restrict__ W1, const float* __restrict__ b1,
    const float* __restrict__ gamma, const float* __restrict__ beta,
    const float* __restrict__ bn_mean, const float* __restrict__ bn_var,
    const float* __restrict__ W2, const float* __restrict__ b2,
    const float* __restrict__ eps_p,
    float* __restrict__ h_out, const float* __restrict__ mask,
    const int* __restrict__ batch, float* __restrict__ pool, int layer)
{
    extern __shared__ float sm[];
    float* sW1 = sm;                 // 4096 floats (64x64)
    float* sW2 = sm + 4096;          // 4096
    float* sZ  = sm + 8192;          // 64 x 65 padded = 4160
    float* sT  = sm + 8192 + 4160;   // 64 x 65 padded = 4160
    __shared__ float sScale[64], sShift[64], sB1[64], sB2[64];

    const int tid = threadIdx.x;
    const int rowBase = blockIdx.x * 64;
    const float epsv = 1.0f + __ldg(eps_p);

    float4* sW1v = (float4*)sW1;
    float4* sW2v = (float4*)sW2;
    const float4* W1v = (const float4*)W1;
    const float4* W2v = (const float4*)W2;
#pragma unroll
    for (int i = 0; i < 4; i++) {
        sW1v[tid + i * 256] = W1v[tid + i * 256];
        sW2v[tid + i * 256] = W2v[tid + i * 256];
    }
    if (tid < 64) {
        float sc = __ldg(gamma + tid) * rsqrtf(__ldg(bn_var + tid) + 1e-5f);
        sScale[tid] = sc;
        sShift[tid] = __ldg(beta + tid) - __ldg(bn_mean + tid) * sc;
        sB1[tid] = __ldg(b1 + tid);
        sB2[tid] = __ldg(b2 + tid);
    }

    // Load z tile = (1+eps)*h + agg
    const float4* h4 = (const float4*)h_in;
    const float4* a4 = (const float4*)agg;
#pragma unroll
    for (int i = 0; i < 4; i++) {
        int t = tid + i * 256;
        int r = t >> 4, c4 = t & 15;
        int gr = rowBase + r;
        float4 z = make_float4(0.f, 0.f, 0.f, 0.f);
        if (gr < Nn) {
            float4 hv = h4[(size_t)gr * 16 + c4];
            float4 av = a4[(size_t)gr * 16 + c4];
            z.x = fmaf(epsv, hv.x, av.x);
            z.y = fmaf(epsv, hv.y, av.y);
            z.z = fmaf(epsv, hv.z, av.z);
            z.w = fmaf(epsv, hv.w, av.w);
        }
        float* dstp = sZ + r * 65 + c4 * 4;
        dstp[0] = z.x; dstp[1] = z.y; dstp[2] = z.z; dstp[3] = z.w;
    }
    __syncthreads();

    const int tx = tid & 15, ty = tid >> 4;
    const int c0 = tx * 4, r0 = ty * 4;

    // ---- GEMM1: acc = z @ W1  (f32x2 packed: cols [c0,c0+1] and [c0+2,c0+3])
    unsigned long long acc01[4] = {}, acc23[4] = {};
    {
        const unsigned long long* sW1d = (const unsigned long long*)sW1;
#pragma unroll 8
        for (int k = 0; k < 64; k++) {
            unsigned long long b01 = sW1d[k * 32 + tx * 2];
            unsigned long long b23 = sW1d[k * 32 + tx * 2 + 1];
#pragma unroll
            for (int i = 0; i < 4; i++) {
                unsigned au = __float_as_uint(sZ[(r0 + i) * 65 + k]);
                unsigned long long aa;
                asm("mov.b64 %0, {%1, %1};" : "=l"(aa) : "r"(au));
                asm("fma.rn.f32x2 %0, %1, %2, %0;" : "+l"(acc01[i]) : "l"(aa), "l"(b01));
                asm("fma.rn.f32x2 %0, %1, %2, %0;" : "+l"(acc23[i]) : "l"(aa), "l"(b23));
            }
        }
    }

    // +b1, BN(eval), ReLU -> sT
#pragma unroll
    for (int i = 0; i < 4; i++) {
        unsigned u0, u1, u2, u3;
        asm("mov.b64 {%0, %1}, %2;" : "=r"(u0), "=r"(u1) : "l"(acc01[i]));
        asm("mov.b64 {%0, %1}, %2;" : "=r"(u2), "=r"(u3) : "l"(acc23[i]));
        float v[4] = {__uint_as_float(u0), __uint_as_float(u1),
                      __uint_as_float(u2), __uint_as_float(u3)};
#pragma unroll
        for (int j = 0; j < 4; j++) {
            int cc = c0 + j;
            float t = v[j] + sB1[cc];
            t = fmaf(t, sScale[cc], sShift[cc]);
            sT[(r0 + i) * 65 + cc] = fmaxf(t, 0.f);
        }
    }
    __syncthreads();

    // ---- GEMM2: acc2 = t @ W2 (f32x2 packed)
    unsigned long long bcc01[4] = {}, bcc23[4] = {};
    {
        const unsigned long long* sW2d = (const unsigned long long*)sW2;
#pragma unroll 8
        for (int k = 0; k < 64; k++) {
            unsigned long long b01 = sW2d[k * 32 + tx * 2];
            unsigned long long b23 = sW2d[k * 32 + tx * 2 + 1];
#pragma unroll
            for (int i = 0; i < 4; i++) {
                unsigned au = __float_as_uint(sT[(r0 + i) * 65 + k]);
                unsigned long long aa;
                asm("mov.b64 %0, {%1, %1};" : "=l"(aa) : "r"(au));
                asm("fma.rn.f32x2 %0, %1, %2, %0;" : "+l"(bcc01[i]) : "l"(aa), "l"(b01));
                asm("fma.rn.f32x2 %0, %1, %2, %0;" : "+l"(bcc23[i]) : "l"(aa), "l"(b23));
            }
        }
    }

    // +b2, ReLU -> stage into sOut (reuse sZ, stride 64). Safe: sZ reads done.
    float* sOut = sZ;
#pragma unroll
    for (int i = 0; i < 4; i++) {
        unsigned u0, u1, u2, u3;
        asm("mov.b64 {%0, %1}, %2;" : "=r"(u0), "=r"(u1) : "l"(bcc01[i]));
        asm("mov.b64 {%0, %1}, %2;" : "=r"(u2), "=r"(u3) : "l"(bcc23[i]));
        float v[4] = {__uint_as_float(u0), __uint_as_float(u1),
                      __uint_as_float(u2), __uint_as_float(u3)};
#pragma unroll
        for (int j = 0; j < 4; j++)
            sOut[(r0 + i) * 64 + c0 + j] = fmaxf(v[j] + sB2[c0 + j], 0.f);
    }
    __syncthreads();

    // Global write (coalesced float4) + pooled add
    float4* sOut4 = (float4*)sOut;
    float4* ho4 = (float4*)h_out;
#pragma unroll
    for (int i = 0; i < 4; i++) {
        int t = tid + i * 256;
        int r = t >> 4, c4 = t & 15;
        int gr = rowBase + r;
        if (gr < Nn) {
            float4 v = sOut4[r * 16 + c4];
            ho4[(size_t)gr * 16 + c4] = v;
            float w = __ldg(mask + gr);
            if (w != 0.f) {
                float* addr = pool + (size_t)__ldg(batch + gr) * POOLW + layer * 128 + c4 * 4;
                float4 p = make_float4(v.x * w, v.y * w, v.z * w, v.w * w);
                asm volatile("red.global.add.v4.f32 [%0], {%1, %2, %3, %4};"
                             :: "l"(addr), "f"(p.x), "f"(p.y), "f"(p.z), "f"(p.w)
                             : "memory");
            }
        }
    }
}

// ---------------------------------------------------------------------------
// Center-node gather: pool[g, layer*128 + 64 + c] = h[mapping[g], c]
// ---------------------------------------------------------------------------
__global__ __launch_bounds__(256) void center_kernel(
    const float4* __restrict__ h4, const int* __restrict__ mapping,
    float4* __restrict__ pool4, int layer)
{
    int t = blockIdx.x * 256 + threadIdx.x;
    if (t >= Gg * 16) return;
    int g = t >> 4, c = t & 15;
    int m = __ldg(mapping + g);
    pool4[g * (POOLW / 4) + layer * 32 + 16 + c] = h4[(size_t)m * 16 + c];
}

// ---------------------------------------------------------------------------
// Final projection: out[g, s] = pool[g, :] @ lin_w[:, s] + lin_b[s]
// ---------------------------------------------------------------------------
__global__ __launch_bounds__(128) void final_kernel(
    const float* __restrict__ pool, const float* __restrict__ lw,
    const float* __restrict__ lb, float* __restrict__ out)
{
    int g = blockIdx.x * 4 + (threadIdx.x >> 5);
    int s = threadIdx.x & 31;
    const float* pr = pool + (size_t)g * POOLW;
    float acc = __ldg(lb + s);
#pragma unroll 4
    for (int k = 0; k < POOLW; k++)
        acc = fmaf(__ldg(pr + k), __ldg(lw + k * Ss + s), acc);
    out[g * Ss + s] = acc;
}

extern "C" void kernel_launch(void* const* d_in, const int* in_sizes, int n_in,
                              void* d_out, int out_size)
{
    const float* x       = (const float*)d_in[0];
    const float* ew      = (const float*)d_in[1];
    const float* mask    = (const float*)d_in[2];
    const float* W1      = (const float*)d_in[3];
    const float* b1      = (const float*)d_in[4];
    const float* gamma   = (const float*)d_in[5];
    const float* beta    = (const float*)d_in[6];
    const float* bn_mean = (const float*)d_in[7];
    const float* bn_var  = (const float*)d_in[8];
    const float* W2      = (const float*)d_in[9];
    const float* b2      = (const float*)d_in[10];
    const float* eps     = (const float*)d_in[11];
    const float* lin_w   = (const float*)d_in[12];
    const float* lin_b   = (const float*)d_in[13];
    const int* edge_index = (const int*)d_in[14];
    const int* batch      = (const int*)d_in[15];
    const int* mapping    = (const int*)d_in[16];
    float* out = (float*)d_out;

    float *hbuf = nullptr, *aggbuf = nullptr, *poolbuf = nullptr;
    (void)cudaGetSymbolAddress((void**)&hbuf, g_h);
    (void)cudaGetSymbolAddress((void**)&aggbuf, g_agg);
    (void)cudaGetSymbolAddress((void**)&poolbuf, g_pool);

    const int SMEM_BYTES = (4096 + 4096 + 4160 + 4160) * (int)sizeof(float); // 66048
    (void)cudaFuncSetAttribute(fused_mlp, cudaFuncAttributeMaxDynamicSharedMemorySize, SMEM_BYTES);

    cudaMemsetAsync(poolbuf, 0, (size_t)Gg * POOLW * sizeof(float));

    const float* h = x;
    for (int l = 0; l < Ll; l++) {
        cudaMemsetAsync(aggbuf, 0, (size_t)Nn * Dd * sizeof(float));
        scatter_kernel<<<(EQ * 16 + 255) / 256, 256>>>(
            (const float4*)h, ew, edge_index, edge_index + Ee, aggbuf);
        fused_mlp<<<(Nn + 63) / 64, 256, SMEM_BYTES>>>(
            h, aggbuf,
            W1 + l * Dd * Dd, b1 + l * Dd,
            gamma + l * Dd, beta + l * Dd, bn_mean + l * Dd, bn_var + l * Dd,
            W2 + l * Dd * Dd, b2 + l * Dd,
            eps + l,
            hbuf, mask, batch, poolbuf, l);
        center_kernel<<<(Gg * 16 + 255) / 256, 256>>>(
            (const float4*)hbuf, mapping, (float4*)poolbuf, l);
        h = hbuf;
    }
    final_kernel<<<Gg / 4, 128>>>(poolbuf, lin_w, lin_b, out);
}

// round 5
// speedup vs baseline: 1.1608x; 1.0656x over previous
#include <cuda_runtime.h>
#include <cuda_bf16.h>
#include <cstdint>

#define Nn 50000
#define Ee 800000
#define Dd 64
#define Ll 3
#define Gg 512
#define Ss 32
#define POOLW (2*Dd*Ll)   // 384
#define EQ (Ee/4)         // 200000 edges per quarter
#define ZPAD 68           // sZ/sT row stride in floats (17 float4s, 16B aligned)

// Scratch (no allocations allowed)
__device__ float g_h[Nn * Dd];
__device__ float g_agg[Nn * Dd];
__device__ float g_pool[Gg * POOLW];

// ---------------------------------------------------------------------------
// Init: agg = (1+eps)*h   (replaces memset; folds the GIN self-term)
// ---------------------------------------------------------------------------
__global__ __launch_bounds__(256) void init_kernel(
    const float4* __restrict__ h4, float4* __restrict__ agg4,
    const float* __restrict__ eps_p)
{
    const float epsv = 1.0f + __ldg(eps_p);
    int i = blockIdx.x * 256 + threadIdx.x;
    if (i < Nn * 16) {
        float4 v = h4[i];
        v.x *= epsv; v.y *= epsv; v.z *= epsv; v.w *= epsv;
        agg4[i] = v;
    }
}

// ---------------------------------------------------------------------------
// Edge scatter: agg[dst] += edge_weight * h[src]
// 16 threads per edge-slot; each thread processes 4 edges (front-batched
// loads -> MLP=4 to hide L2 latency). Vector red.global.add.v4.f32.
// ---------------------------------------------------------------------------
__global__ __launch_bounds__(256) void scatter_kernel(
    const float4* __restrict__ h4, const float* __restrict__ ew,
    const int* __restrict__ src, const int* __restrict__ dst,
    float* __restrict__ agg)
{
    unsigned tid = blockIdx.x * 256u + threadIdx.x;
    unsigned e0 = tid >> 4;
    if (e0 >= EQ) return;
    const int c = tid & 15;

    int s[4], d[4]; float w[4];
#pragma unroll
    for (int q = 0; q < 4; q++) {
        unsigned e = e0 + q * (unsigned)EQ;
        s[q] = __ldg(src + e);
        d[q] = __ldg(dst + e);
        w[q] = __ldg(ew + e);
    }
    float4 v[4];
#pragma unroll
    for (int q = 0; q < 4; q++)
        v[q] = h4[(size_t)s[q] * 16 + c];
#pragma unroll
    for (int q = 0; q < 4; q++) {
        float4 t = v[q];
        t.x *= w[q]; t.y *= w[q]; t.z *= w[q]; t.w *= w[q];
        float* addr = agg + (size_t)d[q] * 64 + c * 4;
        asm volatile("red.global.add.v4.f32 [%0], {%1, %2, %3, %4};"
                     :: "l"(addr), "f"(t.x), "f"(t.y), "f"(t.z), "f"(t.w)
                     : "memory");
    }
}

// ---------------------------------------------------------------------------
// Fused per-layer MLP (z already = (1+eps)h + agg in 'agg'):
//   t = relu(BN(z@W1 + b1)) ; h' = relu(t@W2 + b2)
//   h_out <- h' ; pool[batch[r], layer*128 + c] += h' * mask[r]
// Block = 64 rows. 256 threads as 16x16 grid of 4x4 register tiles.
// FFMA2 accumulators; LDS.128 for both A (4 k at a time) and B operands.
// ---------------------------------------------------------------------------
__global__ __launch_bounds__(256) void fused_mlp(
    const float* __restrict__ zin,
    const float* __restrict__ W1, const float* __restrict__ b1,
    const float* __restrict__ gamma, const float* __restrict__ beta,
    const float* __restrict__ bn_mean, const float* __restrict__ bn_var,
    const float* __restrict__ W2, const float* __restrict__ b2,
    float* __restrict__ h_out, const float* __restrict__ mask,
    const int* __restrict__ batch, float* __restrict__ pool, int layer)
{
    extern __shared__ float sm[];
    float* sW1 = sm;                   // 4096 floats (64x64)
    float* sW2 = sm + 4096;            // 4096
    float* sZ  = sm + 8192;            // 64 x ZPAD = 4352
    float* sT  = sm + 8192 + 64*ZPAD;  // 64 x ZPAD = 4352
    __shared__ float sScale[64], sShift[64], sB1[64], sB2[64];

    const int tid = threadIdx.x;
    const int rowBase = blockIdx.x * 64;

    float4* sW1v = (float4*)sW1;
    float4* sW2v = (float4*)sW2;
    const float4* W1v = (const float4*)W1;
    const float4* W2v = (const float4*)W2;
#pragma unroll
    for (int i = 0; i < 4; i++) {
        sW1v[tid + i * 256] = W1v[tid + i * 256];
        sW2v[tid + i * 256] = W2v[tid + i * 256];
    }
    if (tid < 64) {
        float sc = __ldg(gamma + tid) * rsqrtf(__ldg(bn_var + tid) + 1e-5f);
        sScale[tid] = sc;
        sShift[tid] = __ldg(beta + tid) - __ldg(bn_mean + tid) * sc;
        sB1[tid] = __ldg(b1 + tid);
        sB2[tid] = __ldg(b2 + tid);
    }

    // Load z tile (row-major, stride ZPAD)
    const float4* z4 = (const float4*)zin;
#pragma unroll
    for (int i = 0; i < 4; i++) {
        int t = tid + i * 256;
        int r = t >> 4, c4 = t & 15;
        int gr = rowBase + r;
        float4 z = (gr < Nn) ? z4[(size_t)gr * 16 + c4]
                             : make_float4(0.f, 0.f, 0.f, 0.f);
        *(float4*)&sZ[r * ZPAD + c4 * 4] = z;
    }
    __syncthreads();

    const int tx = tid & 15, ty = tid >> 4;
    const int c0 = tx * 4, r0 = ty * 4;

    // ---- GEMM1: acc = z @ W1 (FFMA2; A via LDS.128 per 4k, B via LDS.128)
    unsigned long long acc01[4] = {}, acc23[4] = {};
    {
        const float4* sZr = (const float4*)sZ;
        const ulonglong2* sW1q = (const ulonglong2*)sW1;
#pragma unroll
        for (int k4 = 0; k4 < 16; k4++) {
            float4 av[4];
#pragma unroll
            for (int i = 0; i < 4; i++)
                av[i] = sZr[(r0 + i) * (ZPAD / 4) + k4];
#pragma unroll
            for (int kk = 0; kk < 4; kk++) {
                ulonglong2 b = sW1q[(k4 * 4 + kk) * 16 + tx];
#pragma unroll
                for (int i = 0; i < 4; i++) {
                    float a = (kk == 0) ? av[i].x : (kk == 1) ? av[i].y
                            : (kk == 2) ? av[i].z : av[i].w;
                    unsigned au = __float_as_uint(a);
                    unsigned long long aa;
                    asm("mov.b64 %0, {%1, %1};" : "=l"(aa) : "r"(au));
                    asm("fma.rn.f32x2 %0, %1, %2, %0;" : "+l"(acc01[i]) : "l"(aa), "l"(b.x));
                    asm("fma.rn.f32x2 %0, %1, %2, %0;" : "+l"(acc23[i]) : "l"(aa), "l"(b.y));
                }
            }
        }
    }

    // +b1, BN(eval), ReLU -> sT (STS.128)
    {
        float4 bb1 = *(const float4*)&sB1[c0];
        float4 scv = *(const float4*)&sScale[c0];
        float4 shv = *(const float4*)&sShift[c0];
#pragma unroll
        for (int i = 0; i < 4; i++) {
            unsigned u0, u1, u2, u3;
            asm("mov.b64 {%0, %1}, %2;" : "=r"(u0), "=r"(u1) : "l"(acc01[i]));
            asm("mov.b64 {%0, %1}, %2;" : "=r"(u2), "=r"(u3) : "l"(acc23[i]));
            float4 v;
            v.x = fmaxf(fmaf(__uint_as_float(u0) + bb1.x, scv.x, shv.x), 0.f);
            v.y = fmaxf(fmaf(__uint_as_float(u1) + bb1.y, scv.y, shv.y), 0.f);
            v.z = fmaxf(fmaf(__uint_as_float(u2) + bb1.z, scv.z, shv.z), 0.f);
            v.w = fmaxf(fmaf(__uint_as_float(u3) + bb1.w, scv.w, shv.w), 0.f);
            *(float4*)&sT[(r0 + i) * ZPAD + c0] = v;
        }
    }
    __syncthreads();

    // ---- GEMM2: acc2 = t @ W2
    unsigned long long bcc01[4] = {}, bcc23[4] = {};
    {
        const float4* sTr = (const float4*)sT;
        const ulonglong2* sW2q = (const ulonglong2*)sW2;
#pragma unroll
        for (int k4 = 0; k4 < 16; k4++) {
            float4 av[4];
#pragma unroll
            for (int i = 0; i < 4; i++)
                av[i] = sTr[(r0 + i) * (ZPAD / 4) + k4];
#pragma unroll
            for (int kk = 0; kk < 4; kk++) {
                ulonglong2 b = sW2q[(k4 * 4 + kk) * 16 + tx];
#pragma unroll
                for (int i = 0; i < 4; i++) {
                    float a = (kk == 0) ? av[i].x : (kk == 1) ? av[i].y
                            : (kk == 2) ? av[i].z : av[i].w;
                    unsigned au = __float_as_uint(a);
                    unsigned long long aa;
                    asm("mov.b64 %0, {%1, %1};" : "=l"(aa) : "r"(au));
                    asm("fma.rn.f32x2 %0, %1, %2, %0;" : "+l"(bcc01[i]) : "l"(aa), "l"(b.x));
                    asm("fma.rn.f32x2 %0, %1, %2, %0;" : "+l"(bcc23[i]) : "l"(aa), "l"(b.y));
                }
            }
        }
    }

    // +b2, ReLU -> stage into sOut (reuse sZ, stride 64). Safe: sZ reads done.
    float* sOut = sZ;
    {
        float4 bb2 = *(const float4*)&sB2[c0];
#pragma unroll
        for (int i = 0; i < 4; i++) {
            unsigned u0, u1, u2, u3;
            asm("mov.b64 {%0, %1}, %2;" : "=r"(u0), "=r"(u1) : "l"(bcc01[i]));
            asm("mov.b64 {%0, %1}, %2;" : "=r"(u2), "=r"(u3) : "l"(bcc23[i]));
            float4 v;
            v.x = fmaxf(__uint_as_float(u0) + bb2.x, 0.f);
            v.y = fmaxf(__uint_as_float(u1) + bb2.y, 0.f);
            v.z = fmaxf(__uint_as_float(u2) + bb2.z, 0.f);
            v.w = fmaxf(__uint_as_float(u3) + bb2.w, 0.f);
            *(float4*)&sOut[(r0 + i) * 64 + c0] = v;
        }
    }
    __syncthreads();

    // Global write (coalesced float4) + pooled add
    float4* sOut4 = (float4*)sOut;
    float4* ho4 = (float4*)h_out;
#pragma unroll
    for (int i = 0; i < 4; i++) {
        int t = tid + i * 256;
        int r = t >> 4, c4 = t & 15;
        int gr = rowBase + r;
        if (gr < Nn) {
            float4 v = sOut4[r * 16 + c4];
            ho4[(size_t)gr * 16 + c4] = v;
            float w = __ldg(mask + gr);
            if (w != 0.f) {
                float* addr = pool + (size_t)__ldg(batch + gr) * POOLW + layer * 128 + c4 * 4;
                float4 p = make_float4(v.x * w, v.y * w, v.z * w, v.w * w);
                asm volatile("red.global.add.v4.f32 [%0], {%1, %2, %3, %4};"
                             :: "l"(addr), "f"(p.x), "f"(p.y), "f"(p.z), "f"(p.w)
                             : "memory");
            }
        }
    }
}

// ---------------------------------------------------------------------------
// Center-node gather: pool[g, layer*128 + 64 + c] = h[mapping[g], c]
// ---------------------------------------------------------------------------
__global__ __launch_bounds__(256) void center_kernel(
    const float4* __restrict__ h4, const int* __restrict__ mapping,
    float4* __restrict__ pool4, int layer)
{
    int t = blockIdx.x * 256 + threadIdx.x;
    if (t >= Gg * 16) return;
    int g = t >> 4, c = t & 15;
    int m = __ldg(mapping + g);
    pool4[g * (POOLW / 4) + layer * 32 + 16 + c] = h4[(size_t)m * 16 + c];
}

// ---------------------------------------------------------------------------
// Final projection: out[g, s] = pool[g, :] @ lin_w[:, s] + lin_b[s]
// ---------------------------------------------------------------------------
__global__ __launch_bounds__(128) void final_kernel(
    const float* __restrict__ pool, const float* __restrict__ lw,
    const float* __restrict__ lb, float* __restrict__ out)
{
    int g = blockIdx.x * 4 + (threadIdx.x >> 5);
    int s = threadIdx.x & 31;
    const float* pr = pool + (size_t)g * POOLW;
    float acc = __ldg(lb + s);
#pragma unroll 4
    for (int k = 0; k < POOLW; k++)
        acc = fmaf(__ldg(pr + k), __ldg(lw + k * Ss + s), acc);
    out[g * Ss + s] = acc;
}

extern "C" void kernel_launch(void* const* d_in, const int* in_sizes, int n_in,
                              void* d_out, int out_size)
{
    const float* x       = (const float*)d_in[0];
    const float* ew      = (const float*)d_in[1];
    const float* mask    = (const float*)d_in[2];
    const float* W1      = (const float*)d_in[3];
    const float* b1      = (const float*)d_in[4];
    const float* gamma   = (const float*)d_in[5];
    const float* beta    = (const float*)d_in[6];
    const float* bn_mean = (const float*)d_in[7];
    const float* bn_var  = (const float*)d_in[8];
    const float* W2      = (const float*)d_in[9];
    const float* b2      = (const float*)d_in[10];
    const float* eps     = (const float*)d_in[11];
    const float* lin_w   = (const float*)d_in[12];
    const float* lin_b   = (const float*)d_in[13];
    const int* edge_index = (const int*)d_in[14];
    const int* batch      = (const int*)d_in[15];
    const int* mapping    = (const int*)d_in[16];
    float* out = (float*)d_out;

    float *hbuf = nullptr, *aggbuf = nullptr, *poolbuf = nullptr;
    (void)cudaGetSymbolAddress((void**)&hbuf, g_h);
    (void)cudaGetSymbolAddress((void**)&aggbuf, g_agg);
    (void)cudaGetSymbolAddress((void**)&poolbuf, g_pool);

    const int SMEM_BYTES = (4096 + 4096 + 64*ZPAD + 64*ZPAD) * (int)sizeof(float); // ~67.6KB
    (void)cudaFuncSetAttribute(fused_mlp, cudaFuncAttributeMaxDynamicSharedMemorySize, SMEM_BYTES);

    cudaMemsetAsync(poolbuf, 0, (size_t)Gg * POOLW * sizeof(float));

    const float* h = x;
    for (int l = 0; l < Ll; l++) {
        init_kernel<<<(Nn * 16 + 255) / 256, 256>>>(
            (const float4*)h, (float4*)aggbuf, eps + l);
        scatter_kernel<<<(EQ * 16 + 255) / 256, 256>>>(
            (const float4*)h, ew, edge_index, edge_index + Ee, aggbuf);
        fused_mlp<<<(Nn + 63) / 64, 256, SMEM_BYTES>>>(
            aggbuf,
            W1 + l * Dd * Dd, b1 + l * Dd,
            gamma + l * Dd, beta + l * Dd, bn_mean + l * Dd, bn_var + l * Dd,
            W2 + l * Dd * Dd, b2 + l * Dd,
            hbuf, mask, batch, poolbuf, l);
        center_kernel<<<(Gg * 16 + 255) / 256, 256>>>(
            (const float4*)hbuf, mapping, (float4*)poolbuf, l);
        h = hbuf;
    }
    final_kernel<<<Gg / 4, 128>>>(poolbuf, lin_w, lin_b, out);
}